// round 14
// baseline (speedup 1.0000x reference)
#include <stdint.h>
#include <cstdint>
#include <cuda_runtime.h>
#include <cuda_bf16.h>
#include <math.h>

#define DD 256
#define KK 32
#define QQ 16
#define NN 8192
#define NCOL 544          // 512 G cols + 32 H cols (bf16 B)

// Hybrid GEMM partition: tensor path rows [0, 40*128), FFMA rows [40*128, 8192)
#define RT_T 40                       // tensor G row tiles
#define NB_TG (RT_T * 4)              // 160 tensor G blocks
#define NB_TH 64                      // tensor H blocks (all rows)
#define NB_F ((64 - RT_T) * 8)        // 192 FFMA blocks (128 rows x 64 cols)
#define NB_ALL (NB_TG + NB_TH + NB_F) // 416

// Scratch (device globals: no allocation allowed in kernel_launch)
__device__ float g_c[KK * QQ];            // c_k = G_k^T mu_k
__device__ float g_Ck[KK];                // per-k constant
__device__ float g_P[NN * KK];            // ||G^T x - c||^2
__device__ float g_HX[NN * KK];           // h_k^T x
__device__ float g_XDX[NN];               // x^T Psi^-1 x
__device__ __align__(16) float g_Bf[DD * 512];            // fp32 G, [d][col]
__device__ __align__(16) __nv_bfloat16 g_Xh[NN * DD];
__device__ __align__(16) __nv_bfloat16 g_Xl[NN * DD];
__device__ __align__(16) __nv_bfloat16 g_Bh[NCOL * DD];   // [col][d]
__device__ __align__(16) __nv_bfloat16 g_Bl[NCOL * DD];

// ---- packed f32x2 helpers ----
#define FMA2(acc, a, b) \
    asm("fma.rn.f32x2 %0, %1, %2, %0;" : "+l"(acc) : "l"(a), "l"(b))
#define PACKDUP(d, f) \
    asm("mov.b64 %0, {%1, %1};" : "=l"(d) : "r"(__float_as_uint(f)))
#define UNPACK2(flo, fhi, v) do { unsigned _lo, _hi; \
    asm("mov.b64 {%0, %1}, %2;" : "=r"(_lo), "=r"(_hi) : "l"(v)); \
    flo = __uint_as_float(_lo); fhi = __uint_as_float(_hi); } while (0)

__device__ __forceinline__ uint32_t smem_u32(const void* p) {
    uint32_t a;
    asm("{ .reg .u64 t; cvta.to.shared.u64 t, %1; cvt.u32.u64 %0, t; }" : "=r"(a) : "l"(p));
    return a;
}

// ldmatrix x4 (baseline PTX, sm_75+)
#define LDM_X4(r, addr) \
    asm volatile("ldmatrix.sync.aligned.m8n8.x4.shared.b16 {%0,%1,%2,%3}, [%4];" \
        : "=r"((r)[0]), "=r"((r)[1]), "=r"((r)[2]), "=r"((r)[3]) : "r"(addr))

// mma.sync bf16 (baseline PTX, sm_80+) — tensor pipe (HMMA)
__device__ __forceinline__ void mma_bf16(float* c, const uint32_t* a, const uint32_t* b) {
    asm volatile(
        "mma.sync.aligned.m16n8k16.row.col.f32.bf16.bf16.f32 "
        "{%0,%1,%2,%3}, {%4,%5,%6,%7}, {%8,%9}, {%0,%1,%2,%3};"
        : "+f"(c[0]), "+f"(c[1]), "+f"(c[2]), "+f"(c[3])
        : "r"(a[0]), "r"(a[1]), "r"(a[2]), "r"(a[3]), "r"(b[0]), "r"(b[1]));
}

__device__ __forceinline__ float warp_sum(float v) {
    v += __shfl_xor_sync(0xffffffffu, v, 16);
    v += __shfl_xor_sync(0xffffffffu, v, 8);
    v += __shfl_xor_sync(0xffffffffu, v, 4);
    v += __shfl_xor_sync(0xffffffffu, v, 2);
    v += __shfl_xor_sync(0xffffffffu, v, 1);
    return v;
}
__device__ __forceinline__ float warp_max(float v) {
    v = fmaxf(v, __shfl_xor_sync(0xffffffffu, v, 16));
    v = fmaxf(v, __shfl_xor_sync(0xffffffffu, v, 8));
    v = fmaxf(v, __shfl_xor_sync(0xffffffffu, v, 4));
    v = fmaxf(v, __shfl_xor_sync(0xffffffffu, v, 2));
    v = fmaxf(v, __shfl_xor_sync(0xffffffffu, v, 1));
    return v;
}

// ---------------------------------------------------------------------------
// Fused pre-pass. Blocks 0..31: per-k setup (scheduled FIRST so the latency-
// bound stragglers start in wave 1). Blocks 32..1055: X convert + xdx.
// ---------------------------------------------------------------------------
__global__ void __launch_bounds__(256) pre_kernel(
    const float* __restrict__ X,
    const float* __restrict__ log_pi,
    const float* __restrict__ mu,
    const float* __restrict__ Lambda,
    const float* __restrict__ log_psi)
{
    __shared__ float Ls[DD][QQ + 1];
    __shared__ float LsW[DD][QQ + 1];
    __shared__ float Msm[QQ][QQ + 1];
    __shared__ float Lch[QQ][QQ + 1];
    __shared__ float invd_s[QQ];
    __shared__ float c_s[QQ];
    __shared__ float s_mdm, s_ldpsi, s_ldM;

    const int t = threadIdx.x;
    const int lane = t & 31;
    const int w = t >> 5;

    if (blockIdx.x >= KK) {
        // ---- X convert + xdx ----
        const int cb = blockIdx.x - KK;
        int i = (cb * 256 + t) * 8;
        float4 a = *reinterpret_cast<const float4*>(X + i);
        float4 b = *reinterpret_cast<const float4*>(X + i + 4);
        float v[8] = {a.x, a.y, a.z, a.w, b.x, b.y, b.z, b.w};

        float xpart = 0.f;
        #pragma unroll
        for (int j = 0; j < 8; j++) {
            float psi = __expf(log_psi[lane * 8 + j]) + 1e-6f + 1e-5f;
            xpart = fmaf(v[j] * v[j], 1.0f / psi, xpart);
        }
        float xdx = warp_sum(xpart);
        if (lane == 0) g_XDX[cb * 8 + w] = xdx;

        uint32_t ph[4], pl[4];
        #pragma unroll
        for (int j = 0; j < 4; j++) {
            __nv_bfloat16 h0 = __float2bfloat16(v[2 * j]);
            __nv_bfloat16 h1 = __float2bfloat16(v[2 * j + 1]);
            __nv_bfloat16 l0 = __float2bfloat16(v[2 * j] - __bfloat162float(h0));
            __nv_bfloat16 l1 = __float2bfloat16(v[2 * j + 1] - __bfloat162float(h1));
            ph[j] = (uint32_t)__bfloat16_as_ushort(h0) | ((uint32_t)__bfloat16_as_ushort(h1) << 16);
            pl[j] = (uint32_t)__bfloat16_as_ushort(l0) | ((uint32_t)__bfloat16_as_ushort(l1) << 16);
        }
        *reinterpret_cast<uint4*>(&g_Xh[i]) = make_uint4(ph[0], ph[1], ph[2], ph[3]);
        *reinterpret_cast<uint4*>(&g_Xl[i]) = make_uint4(pl[0], pl[1], pl[2], pl[3]);
        return;
    }

    // ---- setup for component k ----
    const int k = blockIdx.x;

    float psi = __expf(log_psi[t]) + 1e-6f + 1e-5f;
    float ip = 1.0f / psi;

    if (t == 0) { s_mdm = 0.f; s_ldpsi = 0.f; }
    if (t < QQ) c_s[t] = 0.f;

    {
        const float4* lp = reinterpret_cast<const float4*>(Lambda + ((size_t)k * DD + t) * QQ);
        float4 v0 = lp[0], v1 = lp[1], v2 = lp[2], v3 = lp[3];
        float vv[QQ] = {v0.x,v0.y,v0.z,v0.w, v1.x,v1.y,v1.z,v1.w,
                        v2.x,v2.y,v2.z,v2.w, v3.x,v3.y,v3.z,v3.w};
        #pragma unroll
        for (int i = 0; i < QQ; i++) { Ls[t][i] = vv[i]; LsW[t][i] = ip * vv[i]; }
    }
    __syncthreads();

    {
        float v = warp_sum(__logf(psi));
        if (lane == 0) atomicAdd(&s_ldpsi, v);
    }

    {
        int q1 = t >> 4, q2 = t & 15;
        float s0 = 0.f, s1 = 0.f, s2 = 0.f, s3 = 0.f;
        #pragma unroll 4
        for (int d = 0; d < DD; d += 4) {
            s0 = fmaf(LsW[d + 0][q1], Ls[d + 0][q2], s0);
            s1 = fmaf(LsW[d + 1][q1], Ls[d + 1][q2], s1);
            s2 = fmaf(LsW[d + 2][q1], Ls[d + 2][q2], s2);
            s3 = fmaf(LsW[d + 3][q1], Ls[d + 3][q2], s3);
        }
        Msm[q1][q2] = (s0 + s1) + (s2 + s3) + (q1 == q2 ? 1.0f : 0.0f);
    }
    __syncthreads();

    if (w == 0) {  // warp-parallel Cholesky (16x16)
        float W[QQ];
        #pragma unroll
        for (int j = 0; j < QQ; j++) W[j] = (lane < QQ) ? Msm[lane][j] : 0.f;
        float myd = 1.0f;
        #pragma unroll
        for (int j = 0; j < QQ; j++) {
            float pivot = __shfl_sync(0xffffffffu, W[j], j);
            float rs = rsqrtf(pivot);
            float ljj = pivot * rs;
            float lij;
            if (lane == j)                  { lij = ljj; myd = ljj; invd_s[j] = rs; }
            else if (lane > j && lane < QQ) { lij = W[j] * rs; }
            else                            { lij = 0.f; }
            if (lane < QQ) Lch[lane][j] = lij;
            #pragma unroll
            for (int p = j + 1; p < QQ; p++) {
                float lpj = __shfl_sync(0xffffffffu, lij, p);
                W[p] = fmaf(-lij, lpj, W[p]);
            }
        }
        float ldm = warp_sum(__logf(myd));
        if (lane == 0) s_ldM = 2.0f * ldm;
    }
    __syncthreads();

    {
        float g[QQ];
        #pragma unroll
        for (int i = 0; i < QQ; i++) {
            float v = LsW[t][i];
            #pragma unroll
            for (int p = 0; p < QQ; p++)
                if (p < i) v = fmaf(-Lch[i][p], g[p], v);
            g[i] = v * invd_s[i];
        }
        float mud = mu[(size_t)k * DD + t];

        // bf16 hi/lo transposed B + fp32 B (FFMA path)
        #pragma unroll
        for (int i = 0; i < QQ; i++) {
            __nv_bfloat16 h = __float2bfloat16(g[i]);
            g_Bh[(size_t)(k * QQ + i) * DD + t] = h;
            g_Bl[(size_t)(k * QQ + i) * DD + t] = __float2bfloat16(g[i] - __bfloat162float(h));
            g_Bf[(size_t)t * 512 + k * QQ + i] = g[i];
        }
        {
            float hv = ip * mud;
            __nv_bfloat16 h = __float2bfloat16(hv);
            g_Bh[(size_t)(512 + k) * DD + t] = h;
            g_Bl[(size_t)(512 + k) * DD + t] = __float2bfloat16(hv - __bfloat162float(h));
        }

        #pragma unroll
        for (int i = 0; i < QQ; i++) {
            float v = warp_sum(g[i] * mud);
            if (lane == 0) atomicAdd(&c_s[i], v);
        }
        float vm = warp_sum(ip * mud * mud);
        if (lane == 0) atomicAdd(&s_mdm, vm);
    }
    __syncthreads();

    if (t < QQ) g_c[k * QQ + t] = c_s[t];
    if (t == 0) {
        const float LOG2PI = 1.8378770664093453f;
        g_Ck[k] = log_pi[k] - 0.5f * ((float)DD * LOG2PI + s_ldpsi + s_ldM + s_mdm);
    }
}

// ---------------------------------------------------------------------------
// Hybrid GEMM: tensor-pipe blocks (HMMA bf16 hi/lo, rows 0..RT_T*128 for G +
// all rows for H) run CONCURRENTLY with FMA-pipe blocks (f32x2 fp32, rows
// RT_T*128..8192 for G). Both pipes busy simultaneously.
// ---------------------------------------------------------------------------
#define MATB 10240              // 128 rows * 80B
#define STAGEB (4 * MATB)       // Ah, Al, Bh, Bl
#define GEMM_SMEM (2 * STAGEB)  // 81920B

__global__ void __launch_bounds__(256, 1) gemm_kernel(const float* __restrict__ X)
{
    extern __shared__ char smem[];
    const uint32_t sb = smem_u32(smem);
    __shared__ float csm2[128];

    const int bid = blockIdx.x;
    const int tid = threadIdx.x;
    const int wid = tid >> 5;
    const int lane = tid & 31;

    if (bid < NB_TG) {
        // ================= tensor G tiles: 128 x 128 =================
        const int rowBase = (bid >> 2) * 128;
        const int colBase = (bid & 3) * 128;
        const int wr = wid & 1;
        const int wc = wid >> 1;
        if (tid < 128) csm2[tid] = g_c[colBase + tid];

        float acc[4][4][4];
        #pragma unroll
        for (int mt = 0; mt < 4; mt++)
            #pragma unroll
            for (int nt = 0; nt < 4; nt++)
                #pragma unroll
                for (int c = 0; c < 4; c++) acc[mt][nt][c] = 0.f;

        auto load_stage = [&](int s) {
            const int kbase = s * 32;
            char* buf = smem + (s & 1) * STAGEB;
            #pragma unroll
            for (int tl = 0; tl < 4; tl++) {
                const __nv_bfloat16* src = (tl == 0) ? g_Xh : (tl == 1) ? g_Xl
                                         : (tl == 2) ? g_Bh : g_Bl;
                const int rbase = (tl < 2) ? rowBase : colBase;
                char* dst = buf + tl * MATB;
                #pragma unroll
                for (int i = 0; i < 2; i++) {
                    int idx = tid + i * 256;
                    int row = idx >> 2, quad = idx & 3;
                    uint4 v = *reinterpret_cast<const uint4*>(
                        src + (size_t)(rbase + row) * DD + kbase + quad * 8);
                    *reinterpret_cast<uint4*>(dst + row * 80 + quad * 16) = v;
                }
            }
        };

        load_stage(0);
        __syncthreads();

        for (int s = 0; s < 8; s++) {
            if (s < 7) load_stage(s + 1);
            const uint32_t base = sb + (s & 1) * STAGEB;
            const uint32_t Ah = base, Al = base + MATB;
            const uint32_t Bh = base + 2 * MATB, Bl = base + 3 * MATB;

            #pragma unroll
            for (int kk = 0; kk < 2; kk++) {
                uint32_t ah[4][4], al[4][4], bh[8], bl[8];
                {
                    int row0 = wr * 64 + (lane & 7) + ((lane >> 3) & 1) * 8;
                    int kcol = kk * 16 + ((lane >> 4) & 1) * 8;
                    uint32_t off = (uint32_t)(row0 * 80 + kcol * 2);
                    #pragma unroll
                    for (int mt = 0; mt < 4; mt++) {
                        LDM_X4(ah[mt], Ah + off + mt * (16 * 80));
                        LDM_X4(al[mt], Al + off + mt * (16 * 80));
                    }
                }
                {
                    int n0 = wc * 32 + ((lane >> 4) & 1) * 8 + (lane & 7);
                    int kb = kk * 16 + ((lane >> 3) & 1) * 8;
                    uint32_t off = (uint32_t)(n0 * 80 + kb * 2);
                    LDM_X4(&bh[0], Bh + off);
                    LDM_X4(&bh[4], Bh + off + 16 * 80);
                    LDM_X4(&bl[0], Bl + off);
                    LDM_X4(&bl[4], Bl + off + 16 * 80);
                }
                #pragma unroll
                for (int mt = 0; mt < 4; mt++)
                    #pragma unroll
                    for (int nt = 0; nt < 4; nt++) {
                        mma_bf16(acc[mt][nt], ah[mt], &bh[nt * 2]);
                        mma_bf16(acc[mt][nt], ah[mt], &bl[nt * 2]);
                        mma_bf16(acc[mt][nt], al[mt], &bh[nt * 2]);
                    }
            }
            __syncthreads();
        }

        #pragma unroll
        for (int mt = 0; mt < 4; mt++) {
            int r1 = rowBase + wr * 64 + mt * 16 + (lane >> 2);
            #pragma unroll
            for (int kp = 0; kp < 2; kp++) {
                float p0 = 0.f, p1 = 0.f;
                #pragma unroll
                for (int half = 0; half < 2; half++) {
                    int nt = kp * 2 + half;
                    int gc = wc * 32 + nt * 8 + 2 * (lane & 3);
                    float cc0 = csm2[gc], cc1 = csm2[gc + 1];
                    float e;
                    e = acc[mt][nt][0] - cc0; p0 = fmaf(e, e, p0);
                    e = acc[mt][nt][1] - cc1; p0 = fmaf(e, e, p0);
                    e = acc[mt][nt][2] - cc0; p1 = fmaf(e, e, p1);
                    e = acc[mt][nt][3] - cc1; p1 = fmaf(e, e, p1);
                }
                p0 += __shfl_xor_sync(0xffffffffu, p0, 1);
                p0 += __shfl_xor_sync(0xffffffffu, p0, 2);
                p1 += __shfl_xor_sync(0xffffffffu, p1, 1);
                p1 += __shfl_xor_sync(0xffffffffu, p1, 2);
                if ((lane & 3) == 0) {
                    int kg = (colBase >> 4) + wc * 2 + kp;
                    g_P[(size_t)r1 * KK + kg] = p0;
                    g_P[(size_t)(r1 + 8) * KK + kg] = p1;
                }
            }
        }
    } else if (bid < NB_TG + NB_TH) {
        // ================= tensor H tile: 128 x 32 =================
        const int rowBase = (bid - NB_TG) * 128;
        float acc[4][4];
        #pragma unroll
        for (int nt = 0; nt < 4; nt++)
            #pragma unroll
            for (int c = 0; c < 4; c++) acc[nt][c] = 0.f;

        auto load_stage4 = [&](int s) {
            const int kbase = s * 32;
            char* buf = smem + (s & 1) * STAGEB;
            #pragma unroll
            for (int tl = 0; tl < 2; tl++) {
                const __nv_bfloat16* src = (tl == 0) ? g_Xh : g_Xl;
                char* dst = buf + tl * MATB;
                #pragma unroll
                for (int i = 0; i < 2; i++) {
                    int idx = tid + i * 256;
                    int row = idx >> 2, quad = idx & 3;
                    uint4 v = *reinterpret_cast<const uint4*>(
                        src + (size_t)(rowBase + row) * DD + kbase + quad * 8);
                    *reinterpret_cast<uint4*>(dst + row * 80 + quad * 16) = v;
                }
            }
            {
                int idx = tid;
                int half = idx >> 7;
                int r = (idx & 127) >> 2, quad = idx & 3;
                const __nv_bfloat16* src = half ? g_Bl : g_Bh;
                char* dst = buf + (2 + half) * MATB;
                uint4 v = *reinterpret_cast<const uint4*>(
                    src + (size_t)(512 + r) * DD + kbase + quad * 8);
                *reinterpret_cast<uint4*>(dst + r * 80 + quad * 16) = v;
            }
        };

        load_stage4(0);
        __syncthreads();

        for (int s = 0; s < 8; s++) {
            if (s < 7) load_stage4(s + 1);
            const uint32_t base = sb + (s & 1) * STAGEB;
            const uint32_t Ah = base, Al = base + MATB;
            const uint32_t Bh = base + 2 * MATB, Bl = base + 3 * MATB;

            #pragma unroll
            for (int kk = 0; kk < 2; kk++) {
                uint32_t ah[4], al[4], bh[8], bl[8];
                {
                    int row0 = wid * 16 + (lane & 7) + ((lane >> 3) & 1) * 8;
                    int kcol = kk * 16 + ((lane >> 4) & 1) * 8;
                    uint32_t off = (uint32_t)(row0 * 80 + kcol * 2);
                    LDM_X4(ah, Ah + off);
                    LDM_X4(al, Al + off);
                }
                {
                    int n0 = ((lane >> 4) & 1) * 8 + (lane & 7);
                    int kb = kk * 16 + ((lane >> 3) & 1) * 8;
                    uint32_t off = (uint32_t)(n0 * 80 + kb * 2);
                    LDM_X4(&bh[0], Bh + off);
                    LDM_X4(&bh[4], Bh + off + 16 * 80);
                    LDM_X4(&bl[0], Bl + off);
                    LDM_X4(&bl[4], Bl + off + 16 * 80);
                }
                #pragma unroll
                for (int nt = 0; nt < 4; nt++) {
                    mma_bf16(acc[nt], ah, &bh[nt * 2]);
                    mma_bf16(acc[nt], ah, &bl[nt * 2]);
                    mma_bf16(acc[nt], al, &bh[nt * 2]);
                }
            }
            __syncthreads();
        }

        int r1 = rowBase + wid * 16 + (lane >> 2);
        #pragma unroll
        for (int nt = 0; nt < 4; nt++) {
            int col = nt * 8 + 2 * (lane & 3);
            *reinterpret_cast<float2*>(&g_HX[(size_t)r1 * KK + col]) =
                make_float2(acc[nt][0], acc[nt][1]);
            *reinterpret_cast<float2*>(&g_HX[(size_t)(r1 + 8) * KK + col]) =
                make_float2(acc[nt][2], acc[nt][3]);
        }
    } else {
        // ================= FFMA f32x2 path: 128 rows x 64 G cols =================
        const int f = bid - (NB_TG + NB_TH);
        const int rowBase = (RT_T + (f >> 3)) * 128;
        const int colBase = (f & 7) * 64;
        float* As = reinterpret_cast<float*>(smem);                    // [16][132]
        float* Bs = reinterpret_cast<float*>(smem + 16 * 132 * 4);     // [16][68]

        const int tc = tid & 15;
        const int tr = tid >> 4;

        unsigned long long acc2[4][4];
        #pragma unroll
        for (int i = 0; i < 4; i++)
            #pragma unroll
            for (int j = 0; j < 4; j++) acc2[i][j] = 0ULL;

        for (int d0 = 0; d0 < DD; d0 += 16) {
            #pragma unroll
            for (int i2 = 0; i2 < 2; i2++) {
                int r = (tid >> 2) + i2 * 64;
                int q4 = (tid & 3) * 4;
                float4 v = *reinterpret_cast<const float4*>(
                    &X[(size_t)(rowBase + r) * DD + d0 + q4]);
                As[(q4 + 0) * 132 + r] = v.x;
                As[(q4 + 1) * 132 + r] = v.y;
                As[(q4 + 2) * 132 + r] = v.z;
                As[(q4 + 3) * 132 + r] = v.w;
            }
            {
                int d = tid >> 4, cg = (tid & 15) * 4;
                float4 v = *reinterpret_cast<const float4*>(
                    &g_Bf[(size_t)(d0 + d) * 512 + colBase + cg]);
                *reinterpret_cast<float4*>(&Bs[d * 68 + cg]) = v;
            }
            __syncthreads();

            #pragma unroll
            for (int kk = 0; kk < 16; kk++) {
                unsigned long long a2[4];
                const unsigned long long* ap =
                    reinterpret_cast<const unsigned long long*>(&As[kk * 132 + tr * 8]);
                a2[0] = ap[0]; a2[1] = ap[1]; a2[2] = ap[2]; a2[3] = ap[3];
                float4 bb = *reinterpret_cast<float4*>(&Bs[kk * 68 + tc * 4]);
                unsigned long long b2[4];
                PACKDUP(b2[0], bb.x);
                PACKDUP(b2[1], bb.y);
                PACKDUP(b2[2], bb.z);
                PACKDUP(b2[3], bb.w);
                #pragma unroll
                for (int i = 0; i < 4; i++)
                    #pragma unroll
                    for (int j = 0; j < 4; j++)
                        FMA2(acc2[i][j], a2[i], b2[j]);
            }
            __syncthreads();
        }

        const int kg = (colBase >> 4) + (tc >> 2);
        const int qb = (tc & 3) * 4;
        float c[4];
        #pragma unroll
        for (int j = 0; j < 4; j++) c[j] = g_c[kg * QQ + qb + j];

        #pragma unroll
        for (int i = 0; i < 4; i++) {
            float pv0 = 0.f, pv1 = 0.f;
            #pragma unroll
            for (int j = 0; j < 4; j++) {
                float lo, hi;
                UNPACK2(lo, hi, acc2[i][j]);
                float e0 = lo - c[j], e1 = hi - c[j];
                pv0 = fmaf(e0, e0, pv0);
                pv1 = fmaf(e1, e1, pv1);
            }
            pv0 += __shfl_xor_sync(0xffffffffu, pv0, 1);
            pv0 += __shfl_xor_sync(0xffffffffu, pv0, 2);
            pv1 += __shfl_xor_sync(0xffffffffu, pv1, 1);
            pv1 += __shfl_xor_sync(0xffffffffu, pv1, 2);
            if ((tc & 3) == 0) {
                int r = rowBase + tr * 8 + 2 * i;
                g_P[(size_t)r * KK + kg] = pv0;
                g_P[(size_t)(r + 1) * KK + kg] = pv1;
            }
        }
    }
}

// ---------------------------------------------------------------------------
// Epilogue: combine precomputed P, HX, XDX, Ck; log-softmax over k.
// ---------------------------------------------------------------------------
__global__ void __launch_bounds__(256) epi_kernel(float* __restrict__ out)
{
    const int tid = threadIdx.x;
    const int w = tid >> 5;
    const int lane = tid & 31;
    const float Ck = g_Ck[lane];

    #pragma unroll
    for (int it = 0; it < 4; it++) {
        int n = blockIdx.x * 32 + it * 8 + w;
        float xdx = g_XDX[n];
        float val = Ck + g_HX[(size_t)n * KK + lane]
                  + 0.5f * g_P[(size_t)n * KK + lane] - 0.5f * xdx;

        float m = warp_max(val);
        float s = warp_sum(__expf(val - m));
        float lse = m + __logf(s);

        out[(size_t)n * KK + lane] = val - lse;
        if (lane == 0) out[(size_t)NN * KK + n] = lse;
    }
}

extern "C" void kernel_launch(void* const* d_in, const int* in_sizes, int n_in,
                              void* d_out, int out_size)
{
    const float* X       = (const float*)d_in[0];
    const float* log_pi  = (const float*)d_in[1];
    const float* mu      = (const float*)d_in[2];
    const float* Lambda  = (const float*)d_in[3];
    const float* log_psi = (const float*)d_in[4];
    float* out = (float*)d_out;

    cudaFuncSetAttribute(gemm_kernel, cudaFuncAttributeMaxDynamicSharedMemorySize, GEMM_SMEM);

    pre_kernel<<<1024 + KK, 256>>>(X, log_pi, mu, Lambda, log_psi);
    gemm_kernel<<<NB_ALL, 256, GEMM_SMEM>>>(X);
    epi_kernel<<<NN / 32, 256>>>(out);
}

// round 15
// speedup vs baseline: 1.4433x; 1.4433x over previous
#include <stdint.h>
#include <cstdint>
#include <cuda_runtime.h>
#include <cuda_bf16.h>
#include <math.h>

#define DD 256
#define KK 32
#define QQ 16
#define NN 8192
#define NCOL 544          // 512 G cols + 32 H cols

// Scratch (device globals: no allocation allowed in kernel_launch)
__device__ float g_c[KK * QQ];            // c_k = G_k^T mu_k
__device__ float g_Ck[KK];                // per-k constant
__device__ float g_P[NN * KK];            // ||G^T x - c||^2
__device__ float g_HX[NN * KK];           // h_k^T x
__device__ float g_XDX[NN];               // x^T Psi^-1 x
__device__ __align__(16) __nv_bfloat16 g_Xh[NN * DD];
__device__ __align__(16) __nv_bfloat16 g_Xl[NN * DD];
__device__ __align__(16) __nv_bfloat16 g_Bh[NCOL * DD];   // [col][d]
__device__ __align__(16) __nv_bfloat16 g_Bl[NCOL * DD];

__device__ __forceinline__ uint32_t smem_u32(const void* p) {
    uint32_t a;
    asm("{ .reg .u64 t; cvta.to.shared.u64 t, %1; cvt.u32.u64 %0, t; }" : "=r"(a) : "l"(p));
    return a;
}

// ldmatrix x4 (baseline PTX, sm_75+)
#define LDM_X4(r, addr) \
    asm volatile("ldmatrix.sync.aligned.m8n8.x4.shared.b16 {%0,%1,%2,%3}, [%4];" \
        : "=r"((r)[0]), "=r"((r)[1]), "=r"((r)[2]), "=r"((r)[3]) : "r"(addr))

// mma.sync bf16 (baseline PTX, sm_80+) — tensor pipe (HMMA)
__device__ __forceinline__ void mma_bf16(float* c, const uint32_t* a, const uint32_t* b) {
    asm volatile(
        "mma.sync.aligned.m16n8k16.row.col.f32.bf16.bf16.f32 "
        "{%0,%1,%2,%3}, {%4,%5,%6,%7}, {%8,%9}, {%0,%1,%2,%3};"
        : "+f"(c[0]), "+f"(c[1]), "+f"(c[2]), "+f"(c[3])
        : "r"(a[0]), "r"(a[1]), "r"(a[2]), "r"(a[3]), "r"(b[0]), "r"(b[1]));
}

__device__ __forceinline__ float warp_sum(float v) {
    v += __shfl_xor_sync(0xffffffffu, v, 16);
    v += __shfl_xor_sync(0xffffffffu, v, 8);
    v += __shfl_xor_sync(0xffffffffu, v, 4);
    v += __shfl_xor_sync(0xffffffffu, v, 2);
    v += __shfl_xor_sync(0xffffffffu, v, 1);
    return v;
}
__device__ __forceinline__ float warp_max(float v) {
    v = fmaxf(v, __shfl_xor_sync(0xffffffffu, v, 16));
    v = fmaxf(v, __shfl_xor_sync(0xffffffffu, v, 8));
    v = fmaxf(v, __shfl_xor_sync(0xffffffffu, v, 4));
    v = fmaxf(v, __shfl_xor_sync(0xffffffffu, v, 2));
    v = fmaxf(v, __shfl_xor_sync(0xffffffffu, v, 1));
    return v;
}

// ---------------------------------------------------------------------------
// Fused pre-pass. Blocks 0..31: per-k setup (wave-1 start for the latency-
// bound stragglers). Blocks 32..1055: X convert (bf16 hi/lo) + xdx.
// Slimmed smem (~21KB) so convert blocks stack deeper per SM; convert
// computes inv_psi once per thread into ip_s (1 exp + 1 div per thread).
// ---------------------------------------------------------------------------
__global__ void __launch_bounds__(256) pre_kernel(
    const float* __restrict__ X,
    const float* __restrict__ log_pi,
    const float* __restrict__ mu,
    const float* __restrict__ Lambda,
    const float* __restrict__ log_psi)
{
    __shared__ float ip_s[DD];
    __shared__ float Ls[DD][QQ + 1];
    __shared__ float Msm[QQ][QQ + 1];
    __shared__ float Lch[QQ][QQ + 1];
    __shared__ float invd_s[QQ];
    __shared__ float c_s[QQ];
    __shared__ float s_mdm, s_ldpsi, s_ldM;

    const int t = threadIdx.x;
    const int lane = t & 31;
    const int w = t >> 5;

    // both branches: inv_psi into smem, one exp+div per thread
    float psi = __expf(log_psi[t]) + 1e-6f + 1e-5f;
    float ip = 1.0f / psi;
    ip_s[t] = ip;

    if (blockIdx.x >= KK) {
        // ---- X convert + xdx ----
        __syncthreads();
        const int cb = blockIdx.x - KK;
        int i = (cb * 256 + t) * 8;
        float4 a = *reinterpret_cast<const float4*>(X + i);
        float4 b = *reinterpret_cast<const float4*>(X + i + 4);
        float v[8] = {a.x, a.y, a.z, a.w, b.x, b.y, b.z, b.w};

        float xpart = 0.f;
        #pragma unroll
        for (int j = 0; j < 8; j++)
            xpart = fmaf(v[j] * v[j], ip_s[lane * 8 + j], xpart);
        float xdx = warp_sum(xpart);
        if (lane == 0) g_XDX[cb * 8 + w] = xdx;

        uint32_t ph[4], pl[4];
        #pragma unroll
        for (int j = 0; j < 4; j++) {
            __nv_bfloat16 h0 = __float2bfloat16(v[2 * j]);
            __nv_bfloat16 h1 = __float2bfloat16(v[2 * j + 1]);
            __nv_bfloat16 l0 = __float2bfloat16(v[2 * j] - __bfloat162float(h0));
            __nv_bfloat16 l1 = __float2bfloat16(v[2 * j + 1] - __bfloat162float(h1));
            ph[j] = (uint32_t)__bfloat16_as_ushort(h0) | ((uint32_t)__bfloat16_as_ushort(h1) << 16);
            pl[j] = (uint32_t)__bfloat16_as_ushort(l0) | ((uint32_t)__bfloat16_as_ushort(l1) << 16);
        }
        *reinterpret_cast<uint4*>(&g_Xh[i]) = make_uint4(ph[0], ph[1], ph[2], ph[3]);
        *reinterpret_cast<uint4*>(&g_Xl[i]) = make_uint4(pl[0], pl[1], pl[2], pl[3]);
        return;
    }

    // ---- setup for component k ----
    const int k = blockIdx.x;

    if (t == 0) { s_mdm = 0.f; s_ldpsi = 0.f; }
    if (t < QQ) c_s[t] = 0.f;

    {
        const float4* lp = reinterpret_cast<const float4*>(Lambda + ((size_t)k * DD + t) * QQ);
        float4 v0 = lp[0], v1 = lp[1], v2 = lp[2], v3 = lp[3];
        float vv[QQ] = {v0.x,v0.y,v0.z,v0.w, v1.x,v1.y,v1.z,v1.w,
                        v2.x,v2.y,v2.z,v2.w, v3.x,v3.y,v3.z,v3.w};
        #pragma unroll
        for (int i = 0; i < QQ; i++) Ls[t][i] = vv[i];
    }
    __syncthreads();

    {
        float v = warp_sum(__logf(psi));
        if (lane == 0) atomicAdd(&s_ldpsi, v);
    }

    {
        int q1 = t >> 4, q2 = t & 15;
        float s0 = 0.f, s1 = 0.f, s2 = 0.f, s3 = 0.f;
        #pragma unroll 4
        for (int d = 0; d < DD; d += 4) {
            s0 = fmaf(Ls[d + 0][q1] * ip_s[d + 0], Ls[d + 0][q2], s0);
            s1 = fmaf(Ls[d + 1][q1] * ip_s[d + 1], Ls[d + 1][q2], s1);
            s2 = fmaf(Ls[d + 2][q1] * ip_s[d + 2], Ls[d + 2][q2], s2);
            s3 = fmaf(Ls[d + 3][q1] * ip_s[d + 3], Ls[d + 3][q2], s3);
        }
        Msm[q1][q2] = (s0 + s1) + (s2 + s3) + (q1 == q2 ? 1.0f : 0.0f);
    }
    __syncthreads();

    if (w == 0) {  // warp-parallel Cholesky (16x16)
        float W[QQ];
        #pragma unroll
        for (int j = 0; j < QQ; j++) W[j] = (lane < QQ) ? Msm[lane][j] : 0.f;
        float myd = 1.0f;
        #pragma unroll
        for (int j = 0; j < QQ; j++) {
            float pivot = __shfl_sync(0xffffffffu, W[j], j);
            float rs = rsqrtf(pivot);
            float ljj = pivot * rs;
            float lij;
            if (lane == j)                  { lij = ljj; myd = ljj; invd_s[j] = rs; }
            else if (lane > j && lane < QQ) { lij = W[j] * rs; }
            else                            { lij = 0.f; }
            if (lane < QQ) Lch[lane][j] = lij;
            #pragma unroll
            for (int p = j + 1; p < QQ; p++) {
                float lpj = __shfl_sync(0xffffffffu, lij, p);
                W[p] = fmaf(-lij, lpj, W[p]);
            }
        }
        float ldm = warp_sum(__logf(myd));
        if (lane == 0) s_ldM = 2.0f * ldm;
    }
    __syncthreads();

    {
        float g[QQ];
        #pragma unroll
        for (int i = 0; i < QQ; i++) {
            float v = ip * Ls[t][i];
            #pragma unroll
            for (int p = 0; p < QQ; p++)
                if (p < i) v = fmaf(-Lch[i][p], g[p], v);
            g[i] = v * invd_s[i];
        }
        float mud = mu[(size_t)k * DD + t];

        // transposed bf16 hi/lo: B[col][d], col = k*16+i for G, 512+k for H
        #pragma unroll
        for (int i = 0; i < QQ; i++) {
            __nv_bfloat16 h = __float2bfloat16(g[i]);
            g_Bh[(size_t)(k * QQ + i) * DD + t] = h;
            g_Bl[(size_t)(k * QQ + i) * DD + t] = __float2bfloat16(g[i] - __bfloat162float(h));
        }
        {
            float hv = ip * mud;
            __nv_bfloat16 h = __float2bfloat16(hv);
            g_Bh[(size_t)(512 + k) * DD + t] = h;
            g_Bl[(size_t)(512 + k) * DD + t] = __float2bfloat16(hv - __bfloat162float(h));
        }

        #pragma unroll
        for (int i = 0; i < QQ; i++) {
            float v = warp_sum(g[i] * mud);
            if (lane == 0) atomicAdd(&c_s[i], v);
        }
        float vm = warp_sum(ip * mud * mud);
        if (lane == 0) atomicAdd(&s_mdm, vm);
    }
    __syncthreads();

    if (t < QQ) g_c[k * QQ + t] = c_s[t];
    if (t == 0) {
        const float LOG2PI = 1.8378770664093453f;
        g_Ck[k] = log_pi[k] - 0.5f * ((float)DD * LOG2PI + s_ldpsi + s_ldM + s_mdm);
    }
}

// ---------------------------------------------------------------------------
// HMMA GEMM: D = Xh@Bh^T + Xh@Bl^T + Xl@Bh^T over K=256.  (R13 config)
// Col tiles 0..3: N=128 (G cols), 8 warps m64 x n32, fused P = ||u-c||^2.
// Col tile 4:     N=32  (H cols), 8 warps m16 x n32, writes HX.
// Double-buffered K=32 stages, 80B-padded smem rows (conflict-free ldmatrix).
// ---------------------------------------------------------------------------
#define MATB 10240              // 128 rows * 80B
#define STAGEB (4 * MATB)       // Ah, Al, Bh, Bl
#define GEMM_SMEM (2 * STAGEB)  // 81920B

__global__ void __launch_bounds__(256, 1) gemm_kernel()
{
    extern __shared__ char smem[];
    const uint32_t sb = smem_u32(smem);
    __shared__ float csm2[128];

    const int tid = threadIdx.x;
    const int wid = tid >> 5;
    const int lane = tid & 31;
    const int rowBase = blockIdx.x * 128;
    const int colBase = blockIdx.y * 128;
    const int colTile = blockIdx.y;

    if (colTile < 4) {
        // ================= G tiles: N=128 =================
        const int wr = wid & 1;          // m half (64 rows)
        const int wc = wid >> 1;         // n quarter (32 cols)
        if (tid < 128) csm2[tid] = g_c[colBase + tid];

        float acc[4][4][4];
        #pragma unroll
        for (int mt = 0; mt < 4; mt++)
            #pragma unroll
            for (int nt = 0; nt < 4; nt++)
                #pragma unroll
                for (int c = 0; c < 4; c++) acc[mt][nt][c] = 0.f;

        auto load_stage = [&](int s) {
            const int kbase = s * 32;
            char* buf = smem + (s & 1) * STAGEB;
            #pragma unroll
            for (int tl = 0; tl < 4; tl++) {
                const __nv_bfloat16* src = (tl == 0) ? g_Xh : (tl == 1) ? g_Xl
                                         : (tl == 2) ? g_Bh : g_Bl;
                const int rbase = (tl < 2) ? rowBase : colBase;
                char* dst = buf + tl * MATB;
                #pragma unroll
                for (int i = 0; i < 2; i++) {
                    int idx = tid + i * 256;
                    int row = idx >> 2, quad = idx & 3;
                    uint4 v = *reinterpret_cast<const uint4*>(
                        src + (size_t)(rbase + row) * DD + kbase + quad * 8);
                    *reinterpret_cast<uint4*>(dst + row * 80 + quad * 16) = v;
                }
            }
        };

        load_stage(0);
        __syncthreads();

        for (int s = 0; s < 8; s++) {
            if (s < 7) load_stage(s + 1);
            const uint32_t base = sb + (s & 1) * STAGEB;
            const uint32_t Ah = base, Al = base + MATB;
            const uint32_t Bh = base + 2 * MATB, Bl = base + 3 * MATB;

            #pragma unroll
            for (int kk = 0; kk < 2; kk++) {
                uint32_t ah[4][4], al[4][4], bh[8], bl[8];
                {
                    int row0 = wr * 64 + (lane & 7) + ((lane >> 3) & 1) * 8;
                    int kcol = kk * 16 + ((lane >> 4) & 1) * 8;
                    uint32_t off = (uint32_t)(row0 * 80 + kcol * 2);
                    #pragma unroll
                    for (int mt = 0; mt < 4; mt++) {
                        LDM_X4(ah[mt], Ah + off + mt * (16 * 80));
                        LDM_X4(al[mt], Al + off + mt * (16 * 80));
                    }
                }
                {
                    int n0 = wc * 32 + ((lane >> 4) & 1) * 8 + (lane & 7);
                    int kb = kk * 16 + ((lane >> 3) & 1) * 8;
                    uint32_t off = (uint32_t)(n0 * 80 + kb * 2);
                    LDM_X4(&bh[0], Bh + off);
                    LDM_X4(&bh[4], Bh + off + 16 * 80);
                    LDM_X4(&bl[0], Bl + off);
                    LDM_X4(&bl[4], Bl + off + 16 * 80);
                }
                #pragma unroll
                for (int mt = 0; mt < 4; mt++)
                    #pragma unroll
                    for (int nt = 0; nt < 4; nt++) {
                        mma_bf16(acc[mt][nt], ah[mt], &bh[nt * 2]);
                        mma_bf16(acc[mt][nt], ah[mt], &bl[nt * 2]);
                        mma_bf16(acc[mt][nt], al[mt], &bh[nt * 2]);
                    }
            }
            __syncthreads();
        }

        #pragma unroll
        for (int mt = 0; mt < 4; mt++) {
            int r1 = rowBase + wr * 64 + mt * 16 + (lane >> 2);
            #pragma unroll
            for (int kp = 0; kp < 2; kp++) {
                float p0 = 0.f, p1 = 0.f;
                #pragma unroll
                for (int half = 0; half < 2; half++) {
                    int nt = kp * 2 + half;
                    int gc = wc * 32 + nt * 8 + 2 * (lane & 3);
                    float cc0 = csm2[gc], cc1 = csm2[gc + 1];
                    float e;
                    e = acc[mt][nt][0] - cc0; p0 = fmaf(e, e, p0);
                    e = acc[mt][nt][1] - cc1; p0 = fmaf(e, e, p0);
                    e = acc[mt][nt][2] - cc0; p1 = fmaf(e, e, p1);
                    e = acc[mt][nt][3] - cc1; p1 = fmaf(e, e, p1);
                }
                p0 += __shfl_xor_sync(0xffffffffu, p0, 1);
                p0 += __shfl_xor_sync(0xffffffffu, p0, 2);
                p1 += __shfl_xor_sync(0xffffffffu, p1, 1);
                p1 += __shfl_xor_sync(0xffffffffu, p1, 2);
                if ((lane & 3) == 0) {
                    int kg = (colBase >> 4) + wc * 2 + kp;
                    g_P[(size_t)r1 * KK + kg] = p0;
                    g_P[(size_t)(r1 + 8) * KK + kg] = p1;
                }
            }
        }
    } else {
        // ================= H tile: N=32 =================
        float acc[4][4];
        #pragma unroll
        for (int nt = 0; nt < 4; nt++)
            #pragma unroll
            for (int c = 0; c < 4; c++) acc[nt][c] = 0.f;

        auto load_stage4 = [&](int s) {
            const int kbase = s * 32;
            char* buf = smem + (s & 1) * STAGEB;
            #pragma unroll
            for (int tl = 0; tl < 2; tl++) {
                const __nv_bfloat16* src = (tl == 0) ? g_Xh : g_Xl;
                char* dst = buf + tl * MATB;
                #pragma unroll
                for (int i = 0; i < 2; i++) {
                    int idx = tid + i * 256;
                    int row = idx >> 2, quad = idx & 3;
                    uint4 v = *reinterpret_cast<const uint4*>(
                        src + (size_t)(rowBase + row) * DD + kbase + quad * 8);
                    *reinterpret_cast<uint4*>(dst + row * 80 + quad * 16) = v;
                }
            }
            {
                int idx = tid;
                int half = idx >> 7;
                int r = (idx & 127) >> 2, quad = idx & 3;
                const __nv_bfloat16* src = half ? g_Bl : g_Bh;
                char* dst = buf + (2 + half) * MATB;
                uint4 v = *reinterpret_cast<const uint4*>(
                    src + (size_t)(512 + r) * DD + kbase + quad * 8);
                *reinterpret_cast<uint4*>(dst + r * 80 + quad * 16) = v;
            }
        };

        load_stage4(0);
        __syncthreads();

        for (int s = 0; s < 8; s++) {
            if (s < 7) load_stage4(s + 1);
            const uint32_t base = sb + (s & 1) * STAGEB;
            const uint32_t Ah = base, Al = base + MATB;
            const uint32_t Bh = base + 2 * MATB, Bl = base + 3 * MATB;

            #pragma unroll
            for (int kk = 0; kk < 2; kk++) {
                uint32_t ah[4], al[4], bh[8], bl[8];
                {
                    int row0 = wid * 16 + (lane & 7) + ((lane >> 3) & 1) * 8;
                    int kcol = kk * 16 + ((lane >> 4) & 1) * 8;
                    uint32_t off = (uint32_t)(row0 * 80 + kcol * 2);
                    LDM_X4(ah, Ah + off);
                    LDM_X4(al, Al + off);
                }
                {
                    int n0 = ((lane >> 4) & 1) * 8 + (lane & 7);
                    int kb = kk * 16 + ((lane >> 3) & 1) * 8;
                    uint32_t off = (uint32_t)(n0 * 80 + kb * 2);
                    LDM_X4(&bh[0], Bh + off);
                    LDM_X4(&bh[4], Bh + off + 16 * 80);
                    LDM_X4(&bl[0], Bl + off);
                    LDM_X4(&bl[4], Bl + off + 16 * 80);
                }
                #pragma unroll
                for (int nt = 0; nt < 4; nt++) {
                    mma_bf16(acc[nt], ah, &bh[nt * 2]);
                    mma_bf16(acc[nt], ah, &bl[nt * 2]);
                    mma_bf16(acc[nt], al, &bh[nt * 2]);
                }
            }
            __syncthreads();
        }

        int r1 = rowBase + wid * 16 + (lane >> 2);
        #pragma unroll
        for (int nt = 0; nt < 4; nt++) {
            int col = nt * 8 + 2 * (lane & 3);
            *reinterpret_cast<float2*>(&g_HX[(size_t)r1 * KK + col]) =
                make_float2(acc[nt][0], acc[nt][1]);
            *reinterpret_cast<float2*>(&g_HX[(size_t)(r1 + 8) * KK + col]) =
                make_float2(acc[nt][2], acc[nt][3]);
        }
    }
}

// ---------------------------------------------------------------------------
// Epilogue: combine precomputed P, HX, XDX, Ck; log-softmax over k.
// ---------------------------------------------------------------------------
__global__ void __launch_bounds__(256) epi_kernel(float* __restrict__ out)
{
    const int tid = threadIdx.x;
    const int w = tid >> 5;
    const int lane = tid & 31;
    const float Ck = g_Ck[lane];

    #pragma unroll
    for (int it = 0; it < 4; it++) {
        int n = blockIdx.x * 32 + it * 8 + w;
        float xdx = g_XDX[n];
        float val = Ck + g_HX[(size_t)n * KK + lane]
                  + 0.5f * g_P[(size_t)n * KK + lane] - 0.5f * xdx;

        float m = warp_max(val);
        float s = warp_sum(__expf(val - m));
        float lse = m + __logf(s);

        out[(size_t)n * KK + lane] = val - lse;
        if (lane == 0) out[(size_t)NN * KK + n] = lse;
    }
}

extern "C" void kernel_launch(void* const* d_in, const int* in_sizes, int n_in,
                              void* d_out, int out_size)
{
    const float* X       = (const float*)d_in[0];
    const float* log_pi  = (const float*)d_in[1];
    const float* mu      = (const float*)d_in[2];
    const float* Lambda  = (const float*)d_in[3];
    const float* log_psi = (const float*)d_in[4];
    float* out = (float*)d_out;

    cudaFuncSetAttribute(gemm_kernel, cudaFuncAttributeMaxDynamicSharedMemorySize, GEMM_SMEM);

    pre_kernel<<<1024 + KK, 256>>>(X, log_pi, mu, Lambda, log_psi);
    gemm_kernel<<<dim3(NN / 128, 5), 256, GEMM_SMEM>>>();
    epi_kernel<<<NN / 32, 256>>>(out);
}

// round 17
// speedup vs baseline: 1.4973x; 1.0374x over previous
#include <stdint.h>
#include <cstdint>
#include <cuda_runtime.h>
#include <cuda_bf16.h>
#include <math.h>

#define DD 256
#define KK 32
#define QQ 16
#define NN 8192

// Scratch (device globals: no allocation allowed in kernel_launch)
__device__ float g_c[KK * QQ];            // c_k = G_k^T mu_k
__device__ float g_Ck[KK];                // per-k constant
__device__ float g_ip[DD];                // inv_psi (for epi xdx)
__device__ float g_Mp[8 * KK * 256];      // M partials: [chunk][k][q1*16+q2]
__device__ float g_P[NN * KK];            // ||G^T x - c||^2
__device__ float g_HX[NN * KK];           // h_k^T x
__device__ __align__(16) __nv_bfloat16 g_Bh[544 * DD];   // [col][d]: 512 G + 32 H
__device__ __align__(16) __nv_bfloat16 g_Bl[544 * DD];

__device__ __forceinline__ uint32_t smem_u32(const void* p) {
    uint32_t a;
    asm("{ .reg .u64 t; cvta.to.shared.u64 t, %1; cvt.u32.u64 %0, t; }" : "=r"(a) : "l"(p));
    return a;
}

// ldmatrix x4 (baseline PTX, sm_75+)
#define LDM_X4(r, addr) \
    asm volatile("ldmatrix.sync.aligned.m8n8.x4.shared.b16 {%0,%1,%2,%3}, [%4];" \
        : "=r"((r)[0]), "=r"((r)[1]), "=r"((r)[2]), "=r"((r)[3]) : "r"(addr))

// mma.sync bf16 (baseline PTX, sm_80+) — tensor pipe (HMMA)
__device__ __forceinline__ void mma_bf16(float* c, const uint32_t* a, const uint32_t* b) {
    asm volatile(
        "mma.sync.aligned.m16n8k16.row.col.f32.bf16.bf16.f32 "
        "{%0,%1,%2,%3}, {%4,%5,%6,%7}, {%8,%9}, {%0,%1,%2,%3};"
        : "+f"(c[0]), "+f"(c[1]), "+f"(c[2]), "+f"(c[3])
        : "r"(a[0]), "r"(a[1]), "r"(a[2]), "r"(a[3]), "r"(b[0]), "r"(b[1]));
}

__device__ __forceinline__ float warp_sum(float v) {
    v += __shfl_xor_sync(0xffffffffu, v, 16);
    v += __shfl_xor_sync(0xffffffffu, v, 8);
    v += __shfl_xor_sync(0xffffffffu, v, 4);
    v += __shfl_xor_sync(0xffffffffu, v, 2);
    v += __shfl_xor_sync(0xffffffffu, v, 1);
    return v;
}
__device__ __forceinline__ float warp_max(float v) {
    v = fmaxf(v, __shfl_xor_sync(0xffffffffu, v, 16));
    v = fmaxf(v, __shfl_xor_sync(0xffffffffu, v, 8));
    v = fmaxf(v, __shfl_xor_sync(0xffffffffu, v, 4));
    v = fmaxf(v, __shfl_xor_sync(0xffffffffu, v, 2));
    v = fmaxf(v, __shfl_xor_sync(0xffffffffu, v, 1));
    return v;
}

// ---------------------------------------------------------------------------
// pre1: wide M-build. Block (k, chunk) computes the 16x16 partial
// sum_{d in chunk} Lam[d][q1] * ip[d] * Lam[d][q2] into its own g_Mp slice.
// 256 blocks; no atomics, no zeroing (full overwrite each launch).
// ---------------------------------------------------------------------------
__global__ void __launch_bounds__(256) pre1_kernel(
    const float* __restrict__ Lambda, const float* __restrict__ log_psi)
{
    __shared__ float Lc[32][QQ + 1];
    __shared__ float ipc[32];

    const int k = blockIdx.x >> 3;
    const int ch = blockIdx.x & 7;
    const int t = threadIdx.x;
    const int d0 = ch * 32;

    {   // stage 32 rows x 16 q of Lambda
        int r = t >> 3, qp = (t & 7) * 2;
        const float2 v = *reinterpret_cast<const float2*>(
            Lambda + ((size_t)k * DD + d0 + r) * QQ + qp);
        Lc[r][qp] = v.x; Lc[r][qp + 1] = v.y;
    }
    if (t < 32)
        ipc[t] = 1.0f / ((__expf(log_psi[d0 + t]) + 1e-6f) + 1e-5f);
    __syncthreads();

    const int q1 = t >> 4, q2 = t & 15;
    float s0 = 0.f, s1 = 0.f, s2 = 0.f, s3 = 0.f;
    #pragma unroll
    for (int r = 0; r < 32; r += 4) {
        s0 = fmaf(Lc[r + 0][q1] * ipc[r + 0], Lc[r + 0][q2], s0);
        s1 = fmaf(Lc[r + 1][q1] * ipc[r + 1], Lc[r + 1][q2], s1);
        s2 = fmaf(Lc[r + 2][q1] * ipc[r + 2], Lc[r + 2][q2], s2);
        s3 = fmaf(Lc[r + 3][q1] * ipc[r + 3], Lc[r + 3][q2], s3);
    }
    g_Mp[((size_t)ch * KK + k) * 256 + t] = (s0 + s1) + (s2 + s3);
}

// ---------------------------------------------------------------------------
// pre2: per-k narrow phase. Sum M partials, Cholesky (warp-parallel),
// forward-solve G rows, write bf16 hi/lo B = [G | H], c, Ck, ip.
// ---------------------------------------------------------------------------
__global__ void __launch_bounds__(256) pre2_kernel(
    const float* __restrict__ log_pi,
    const float* __restrict__ mu,
    const float* __restrict__ Lambda,
    const float* __restrict__ log_psi)
{
    __shared__ float Msm[QQ][QQ + 1];
    __shared__ float Lch[QQ][QQ + 1];
    __shared__ float invd_s[QQ];
    __shared__ float c_s[QQ];
    __shared__ float s_mdm, s_ldpsi, s_ldM;

    const int k = blockIdx.x;
    const int t = threadIdx.x;
    const int lane = t & 31;
    const int w = t >> 5;

    float psi = (__expf(log_psi[t]) + 1e-6f) + 1e-5f;
    float ip = 1.0f / psi;
    if (k == 0) g_ip[t] = ip;

    if (t == 0) { s_mdm = 0.f; s_ldpsi = 0.f; }
    if (t < QQ) c_s[t] = 0.f;

    {   // M = I + sum of 8 partials
        float m = ((t >> 4) == (t & 15)) ? 1.0f : 0.0f;
        #pragma unroll
        for (int c = 0; c < 8; c++)
            m += g_Mp[((size_t)c * KK + k) * 256 + t];
        Msm[t >> 4][t & 15] = m;
    }
    __syncthreads();

    {
        float v = warp_sum(__logf(psi));
        if (lane == 0) atomicAdd(&s_ldpsi, v);
    }

    if (w == 0) {  // warp-parallel Cholesky (16x16)
        float W[QQ];
        #pragma unroll
        for (int j = 0; j < QQ; j++) W[j] = (lane < QQ) ? Msm[lane][j] : 0.f;
        float myd = 1.0f;
        #pragma unroll
        for (int j = 0; j < QQ; j++) {
            float pivot = __shfl_sync(0xffffffffu, W[j], j);
            float rs = rsqrtf(pivot);
            float ljj = pivot * rs;
            float lij;
            if (lane == j)                  { lij = ljj; myd = ljj; invd_s[j] = rs; }
            else if (lane > j && lane < QQ) { lij = W[j] * rs; }
            else                            { lij = 0.f; }
            if (lane < QQ) Lch[lane][j] = lij;
            #pragma unroll
            for (int p = j + 1; p < QQ; p++) {
                float lpj = __shfl_sync(0xffffffffu, lij, p);
                W[p] = fmaf(-lij, lpj, W[p]);
            }
        }
        float ldm = warp_sum(__logf(myd));
        if (lane == 0) s_ldM = 2.0f * ldm;
    }
    __syncthreads();

    {   // row t of G: forward solve L g = ip * Lambda[t,:]
        float vv[QQ];
        {
            const float4* lp = reinterpret_cast<const float4*>(
                Lambda + ((size_t)k * DD + t) * QQ);
            float4 v0 = lp[0], v1 = lp[1], v2 = lp[2], v3 = lp[3];
            vv[0]=v0.x; vv[1]=v0.y; vv[2]=v0.z; vv[3]=v0.w;
            vv[4]=v1.x; vv[5]=v1.y; vv[6]=v1.z; vv[7]=v1.w;
            vv[8]=v2.x; vv[9]=v2.y; vv[10]=v2.z; vv[11]=v2.w;
            vv[12]=v3.x; vv[13]=v3.y; vv[14]=v3.z; vv[15]=v3.w;
        }
        float g[QQ];
        #pragma unroll
        for (int i = 0; i < QQ; i++) {
            float v = ip * vv[i];
            #pragma unroll
            for (int p = 0; p < QQ; p++)
                if (p < i) v = fmaf(-Lch[i][p], g[p], v);
            g[i] = v * invd_s[i];
        }
        float mud = mu[(size_t)k * DD + t];

        // bf16 hi/lo transposed: B[col][d], col = k*16+i for G, 512+k for H
        #pragma unroll
        for (int i = 0; i < QQ; i++) {
            __nv_bfloat16 h = __float2bfloat16(g[i]);
            g_Bh[(size_t)(k * QQ + i) * DD + t] = h;
            g_Bl[(size_t)(k * QQ + i) * DD + t] = __float2bfloat16(g[i] - __bfloat162float(h));
        }
        {
            float hv = ip * mud;
            __nv_bfloat16 h = __float2bfloat16(hv);
            g_Bh[(size_t)(512 + k) * DD + t] = h;
            g_Bl[(size_t)(512 + k) * DD + t] = __float2bfloat16(hv - __bfloat162float(h));
        }

        #pragma unroll
        for (int i = 0; i < QQ; i++) {
            float v = warp_sum(g[i] * mud);
            if (lane == 0) atomicAdd(&c_s[i], v);
        }
        float vm = warp_sum(ip * mud * mud);
        if (lane == 0) atomicAdd(&s_mdm, vm);
    }
    __syncthreads();

    if (t < QQ) g_c[k * QQ + t] = c_s[t];
    if (t == 0) {
        const float LOG2PI = 1.8378770664093453f;
        g_Ck[k] = log_pi[k] - 0.5f * ((float)DD * LOG2PI + s_ldpsi + s_ldM + s_mdm);
    }
}

// ---------------------------------------------------------------------------
// HMMA GEMM, 64x128 CTA tiles, on-the-fly fp32 -> bf16 hi/lo A conversion.
// D = Xh@Bh^T + Xh@Bl^T + Xl@Bh^T over K=256, double-buffered K=32 stages.
// Col tiles 0..3: N=128 G cols, warp tile m32 x n32, fused P = ||u-c||^2.
// Col tile 4:     N=32  H cols, warp tile m16 x n16, writes HX.
// 80B-padded smem rows (conflict-free ldmatrix).
// ---------------------------------------------------------------------------
#define A_B 5120                 // 64 rows * 80B
#define B_B 10240                // 128 rows * 80B
#define STAGEB (2 * A_B + 2 * B_B)   // 30720
#define GEMM_SMEM (2 * STAGEB)       // 61440

__global__ void __launch_bounds__(256) gemm_kernel(const float* __restrict__ X)
{
    extern __shared__ char smem[];
    const uint32_t sb = smem_u32(smem);
    __shared__ float csm2[128];

    const int tid = threadIdx.x;
    const int wid = tid >> 5;
    const int lane = tid & 31;
    const int rowBase = blockIdx.x * 64;
    const int colTile = blockIdx.y;
    const int colBase = colTile * 128;

    // A loader: fp32 X -> truncation-split bf16 hi/lo into smem (both branches)
    auto loadA = [&](int s) {
        const int kbase = s * 32;
        char* buf = smem + (s & 1) * STAGEB;
        int row = tid >> 2, part = tid & 3;          // 256 octs = 64 rows x 4
        const float* srcp = X + (size_t)(rowBase + row) * DD + kbase + part * 8;
        float4 v0 = *reinterpret_cast<const float4*>(srcp);
        float4 v1 = *reinterpret_cast<const float4*>(srcp + 4);
        float f[8] = {v0.x, v0.y, v0.z, v0.w, v1.x, v1.y, v1.z, v1.w};
        uint32_t hi[4], lo[4];
        #pragma unroll
        for (int j = 0; j < 4; j++) {
            uint32_t a = __float_as_uint(f[2 * j]), b = __float_as_uint(f[2 * j + 1]);
            asm("prmt.b32 %0, %1, %2, 0x7632;" : "=r"(hi[j]) : "r"(a), "r"(b));
            float l0 = f[2 * j]     - __uint_as_float(a & 0xFFFF0000u);
            float l1 = f[2 * j + 1] - __uint_as_float(b & 0xFFFF0000u);
            asm("cvt.rn.bf16x2.f32 %0, %1, %2;" : "=r"(lo[j]) : "f"(l1), "f"(l0));
        }
        uint32_t off = row * 80 + part * 16;
        *reinterpret_cast<uint4*>(buf + off)       = make_uint4(hi[0], hi[1], hi[2], hi[3]);
        *reinterpret_cast<uint4*>(buf + A_B + off) = make_uint4(lo[0], lo[1], lo[2], lo[3]);
    };

    if (colTile < 4) {
        // ================= G tiles: 64 x 128 =================
        const int wr = wid & 1;          // m half (32 rows)
        const int wc = wid >> 1;         // n quarter (32 cols)
        if (tid < 128) csm2[tid] = g_c[colBase + tid];

        auto loadBG = [&](int s) {
            const int kbase = s * 32;
            char* buf = smem + (s & 1) * STAGEB + 2 * A_B;
            #pragma unroll
            for (int tl = 0; tl < 2; tl++) {
                const __nv_bfloat16* src = tl ? g_Bl : g_Bh;
                char* dst = buf + tl * B_B;
                #pragma unroll
                for (int i = 0; i < 2; i++) {
                    int idx = tid + i * 256;
                    int row = idx >> 2, quad = idx & 3;
                    uint4 v = *reinterpret_cast<const uint4*>(
                        src + (size_t)(colBase + row) * DD + kbase + quad * 8);
                    *reinterpret_cast<uint4*>(dst + row * 80 + quad * 16) = v;
                }
            }
        };

        float acc[2][4][4];
        #pragma unroll
        for (int mt = 0; mt < 2; mt++)
            #pragma unroll
            for (int nt = 0; nt < 4; nt++)
                #pragma unroll
                for (int c = 0; c < 4; c++) acc[mt][nt][c] = 0.f;

        loadA(0); loadBG(0);
        __syncthreads();

        for (int s = 0; s < 8; s++) {
            if (s < 7) { loadA(s + 1); loadBG(s + 1); }
            const uint32_t base = sb + (s & 1) * STAGEB;
            const uint32_t Ah = base, Al = base + A_B;
            const uint32_t Bh = base + 2 * A_B, Bl = base + 2 * A_B + B_B;

            #pragma unroll
            for (int kk = 0; kk < 2; kk++) {
                uint32_t ah[2][4], al[2][4], bh[8], bl[8];
                {
                    int row0 = wr * 32 + (lane & 7) + ((lane >> 3) & 1) * 8;
                    int kcol = kk * 16 + ((lane >> 4) & 1) * 8;
                    uint32_t off = (uint32_t)(row0 * 80 + kcol * 2);
                    #pragma unroll
                    for (int mt = 0; mt < 2; mt++) {
                        LDM_X4(ah[mt], Ah + off + mt * (16 * 80));
                        LDM_X4(al[mt], Al + off + mt * (16 * 80));
                    }
                }
                {
                    int n0 = wc * 32 + ((lane >> 4) & 1) * 8 + (lane & 7);
                    int kb = kk * 16 + ((lane >> 3) & 1) * 8;
                    uint32_t off = (uint32_t)(n0 * 80 + kb * 2);
                    LDM_X4(&bh[0], Bh + off);
                    LDM_X4(&bh[4], Bh + off + 16 * 80);
                    LDM_X4(&bl[0], Bl + off);
                    LDM_X4(&bl[4], Bl + off + 16 * 80);
                }
                #pragma unroll
                for (int mt = 0; mt < 2; mt++)
                    #pragma unroll
                    for (int nt = 0; nt < 4; nt++) {
                        mma_bf16(acc[mt][nt], ah[mt], &bh[nt * 2]);
                        mma_bf16(acc[mt][nt], ah[mt], &bl[nt * 2]);
                        mma_bf16(acc[mt][nt], al[mt], &bh[nt * 2]);
                    }
            }
            __syncthreads();
        }

        #pragma unroll
        for (int mt = 0; mt < 2; mt++) {
            int r1 = rowBase + wr * 32 + mt * 16 + (lane >> 2);
            #pragma unroll
            for (int kp = 0; kp < 2; kp++) {
                float p0 = 0.f, p1 = 0.f;
                #pragma unroll
                for (int half = 0; half < 2; half++) {
                    int nt = kp * 2 + half;
                    int gc = wc * 32 + nt * 8 + 2 * (lane & 3);
                    float cc0 = csm2[gc], cc1 = csm2[gc + 1];
                    float e;
                    e = acc[mt][nt][0] - cc0; p0 = fmaf(e, e, p0);
                    e = acc[mt][nt][1] - cc1; p0 = fmaf(e, e, p0);
                    e = acc[mt][nt][2] - cc0; p1 = fmaf(e, e, p1);
                    e = acc[mt][nt][3] - cc1; p1 = fmaf(e, e, p1);
                }
                p0 += __shfl_xor_sync(0xffffffffu, p0, 1);
                p0 += __shfl_xor_sync(0xffffffffu, p0, 2);
                p1 += __shfl_xor_sync(0xffffffffu, p1, 1);
                p1 += __shfl_xor_sync(0xffffffffu, p1, 2);
                if ((lane & 3) == 0) {
                    int kg = (colBase >> 4) + wc * 2 + kp;
                    g_P[(size_t)r1 * KK + kg] = p0;
                    g_P[(size_t)(r1 + 8) * KK + kg] = p1;
                }
            }
        }
    } else {
        // ================= H tile: 64 x 32 =================
        const int wr4 = wid & 3;         // m quarter (16 rows)
        const int wc2 = wid >> 2;        // n half (16 cols)

        auto loadBH = [&](int s) {
            const int kbase = s * 32;
            char* buf = smem + (s & 1) * STAGEB + 2 * A_B;
            int half = tid >> 7;
            int r = (tid & 127) >> 2, quad = tid & 3;
            const __nv_bfloat16* src = half ? g_Bl : g_Bh;
            char* dst = buf + half * B_B;
            uint4 v = *reinterpret_cast<const uint4*>(
                src + (size_t)(512 + r) * DD + kbase + quad * 8);
            *reinterpret_cast<uint4*>(dst + r * 80 + quad * 16) = v;
        };

        float acc[2][4];
        #pragma unroll
        for (int nt = 0; nt < 2; nt++)
            #pragma unroll
            for (int c = 0; c < 4; c++) acc[nt][c] = 0.f;

        loadA(0); loadBH(0);
        __syncthreads();

        for (int s = 0; s < 8; s++) {
            if (s < 7) { loadA(s + 1); loadBH(s + 1); }
            const uint32_t base = sb + (s & 1) * STAGEB;
            const uint32_t Ah = base, Al = base + A_B;
            const uint32_t Bh = base + 2 * A_B, Bl = base + 2 * A_B + B_B;

            #pragma unroll
            for (int kk = 0; kk < 2; kk++) {
                uint32_t ah[4], al[4], bh[4], bl[4];
                {
                    int row0 = wr4 * 16 + (lane & 7) + ((lane >> 3) & 1) * 8;
                    int kcol = kk * 16 + ((lane >> 4) & 1) * 8;
                    uint32_t off = (uint32_t)(row0 * 80 + kcol * 2);
                    LDM_X4(ah, Ah + off);
                    LDM_X4(al, Al + off);
                }
                {
                    int n0 = wc2 * 16 + ((lane >> 4) & 1) * 8 + (lane & 7);
                    int kb = kk * 16 + ((lane >> 3) & 1) * 8;
                    uint32_t off = (uint32_t)(n0 * 80 + kb * 2);
                    LDM_X4(bh, Bh + off);
                    LDM_X4(bl, Bl + off);
                }
                #pragma unroll
                for (int nt = 0; nt < 2; nt++) {
                    mma_bf16(acc[nt], ah, &bh[nt * 2]);
                    mma_bf16(acc[nt], ah, &bl[nt * 2]);
                    mma_bf16(acc[nt], al, &bh[nt * 2]);
                }
            }
            __syncthreads();
        }

        int r1 = rowBase + wr4 * 16 + (lane >> 2);
        #pragma unroll
        for (int nt = 0; nt < 2; nt++) {
            int col = wc2 * 16 + nt * 8 + 2 * (lane & 3);
            *reinterpret_cast<float2*>(&g_HX[(size_t)r1 * KK + col]) =
                make_float2(acc[nt][0], acc[nt][1]);
            *reinterpret_cast<float2*>(&g_HX[(size_t)(r1 + 8) * KK + col]) =
                make_float2(acc[nt][2], acc[nt][3]);
        }
    }
}

// ---------------------------------------------------------------------------
// Epilogue: xdx = x^T Psi^-1 x (from X + g_ip), combine with P, HX, Ck;
// log-softmax over k. One warp per row; 8 warps x 4 rows; grid 256.
// ---------------------------------------------------------------------------
__global__ void __launch_bounds__(256) epi_kernel(
    const float* __restrict__ X, float* __restrict__ out)
{
    const int tid = threadIdx.x;
    const int w = tid >> 5;
    const int lane = tid & 31;
    const float Ck = g_Ck[lane];
    const float4 ipa = *reinterpret_cast<const float4*>(&g_ip[lane * 8]);
    const float4 ipb = *reinterpret_cast<const float4*>(&g_ip[lane * 8 + 4]);

    #pragma unroll
    for (int it = 0; it < 4; it++) {
        int n = blockIdx.x * 32 + it * 8 + w;

        float4 xa = *reinterpret_cast<const float4*>(&X[(size_t)n * DD + lane * 8]);
        float4 xb = *reinterpret_cast<const float4*>(&X[(size_t)n * DD + lane * 8 + 4]);
        float xp = 0.f;
        xp = fmaf(ipa.x * xa.x, xa.x, xp);
        xp = fmaf(ipa.y * xa.y, xa.y, xp);
        xp = fmaf(ipa.z * xa.z, xa.z, xp);
        xp = fmaf(ipa.w * xa.w, xa.w, xp);
        xp = fmaf(ipb.x * xb.x, xb.x, xp);
        xp = fmaf(ipb.y * xb.y, xb.y, xp);
        xp = fmaf(ipb.z * xb.z, xb.z, xp);
        xp = fmaf(ipb.w * xb.w, xb.w, xp);
        float xdx = warp_sum(xp);

        float val = Ck + g_HX[(size_t)n * KK + lane]
                  + 0.5f * g_P[(size_t)n * KK + lane] - 0.5f * xdx;

        float m = warp_max(val);
        float s = warp_sum(__expf(val - m));
        float lse = m + __logf(s);

        out[(size_t)n * KK + lane] = val - lse;
        if (lane == 0) out[(size_t)NN * KK + n] = lse;
    }
}

extern "C" void kernel_launch(void* const* d_in, const int* in_sizes, int n_in,
                              void* d_out, int out_size)
{
    const float* X       = (const float*)d_in[0];
    const float* log_pi  = (const float*)d_in[1];
    const float* mu      = (const float*)d_in[2];
    const float* Lambda  = (const float*)d_in[3];
    const float* log_psi = (const float*)d_in[4];
    float* out = (float*)d_out;

    cudaFuncSetAttribute(gemm_kernel, cudaFuncAttributeMaxDynamicSharedMemorySize, GEMM_SMEM);

    pre1_kernel<<<8 * KK, 256>>>(Lambda, log_psi);
    pre2_kernel<<<KK, 256>>>(log_pi, mu, Lambda, log_psi);
    gemm_kernel<<<dim3(NN / 64, 5), 256, GEMM_SMEM>>>(X);
    epi_kernel<<<NN / 32, 256>>>(X, out);
}